// round 1
// baseline (speedup 1.0000x reference)
#include <cuda_runtime.h>

// ---------------------------------------------------------------------------
// MoE layer, top-2 of 8 experts. T=8192 tokens, D=1024, H=4096.
// Pipeline: gate -> offsets(+loss) -> scatter -> GEMM1(gate&up) -> silu*up ->
//           GEMM2(down, scaled atomic accumulate into out).
// All fp32 FFMA this round (precision-safe baseline); grouped-GEMM over
// expert segments padded to BM so tiles never straddle experts.
// ---------------------------------------------------------------------------

#define T_TOK 8192
#define DIM   1024
#define HID   4096
#define NEXP  8

#define BM 128
#define BN 128
#define BK 16
#define NMPAD  136                 // max padded M tiles: (2*T + 8*BM)/BM
#define MAXPAD (NMPAD * BM)        // 17408 slots

// Scratch (static device globals; no runtime allocation allowed)
__device__ float g_hg[(size_t)MAXPAD * HID];   // gate proj, then h after silu
__device__ float g_hu[(size_t)MAXPAD * HID];   // up proj
__device__ int   g_perm[MAXPAD];               // slot -> token (-1 = pad)
__device__ float g_permw[MAXPAD];              // slot combine weight
__device__ int   g_offpad[NEXP + 1];           // padded expert segment starts
__device__ int   g_cnt[NEXP];
__device__ int   g_cursor[NEXP];
__device__ float g_probsum[NEXP];
__device__ int   g_topi[T_TOK * 2];
__device__ float g_topw[T_TOK * 2];

// ---------------------------------------------------------------------------
__global__ void k_init() {
    int i = blockIdx.x * blockDim.x + threadIdx.x;
    if (i < NEXP) { g_cnt[i] = 0; g_cursor[i] = 0; g_probsum[i] = 0.f; }
    if (i < MAXPAD) g_perm[i] = -1;
}

__global__ void k_zero_out(float4* out, int n4) {
    float4 z = make_float4(0.f, 0.f, 0.f, 0.f);
    for (int i = blockIdx.x * blockDim.x + threadIdx.x; i < n4;
         i += gridDim.x * blockDim.x)
        out[i] = z;
}

// ---------------------------------------------------------------------------
// Gating: one warp per token. 8 logits via butterfly reduce, full softmax for
// mean_probs, top-2 (first-index tie rule, matching lax.top_k), top-2 softmax.
__global__ void k_gate(const float* __restrict__ x, const float* __restrict__ gw) {
    int gwarp = (blockIdx.x * blockDim.x + threadIdx.x) >> 5;
    int lane  = threadIdx.x & 31;
    if (gwarp >= T_TOK) return;
    const float* xr = x + (size_t)gwarp * DIM;

    float acc[NEXP];
#pragma unroll
    for (int e = 0; e < NEXP; e++) acc[e] = 0.f;
    for (int i = lane; i < DIM; i += 32) {
        float xv = xr[i];
        float4 g0 = *(const float4*)(gw + (size_t)i * NEXP);
        float4 g1 = *(const float4*)(gw + (size_t)i * NEXP + 4);
        acc[0] += xv * g0.x; acc[1] += xv * g0.y;
        acc[2] += xv * g0.z; acc[3] += xv * g0.w;
        acc[4] += xv * g1.x; acc[5] += xv * g1.y;
        acc[6] += xv * g1.z; acc[7] += xv * g1.w;
    }
#pragma unroll
    for (int off = 16; off > 0; off >>= 1) {
#pragma unroll
        for (int e = 0; e < NEXP; e++)
            acc[e] += __shfl_xor_sync(0xffffffffu, acc[e], off);
    }

    float mx = acc[0];
#pragma unroll
    for (int e = 1; e < NEXP; e++) mx = fmaxf(mx, acc[e]);
    float p[NEXP], s = 0.f;
#pragma unroll
    for (int e = 0; e < NEXP; e++) { p[e] = __expf(acc[e] - mx); s += p[e]; }
    float inv = 1.f / s;
    if (lane < NEXP) atomicAdd(&g_probsum[lane], p[lane] * inv);

    if (lane == 0) {
        int i0 = 0;
#pragma unroll
        for (int e = 1; e < NEXP; e++) if (acc[e] > acc[i0]) i0 = e;
        int i1 = (i0 == 0) ? 1 : 0;
#pragma unroll
        for (int e = 0; e < NEXP; e++)
            if (e != i0 && acc[e] > acc[i1]) i1 = e;
        float m2 = fmaxf(acc[i0], acc[i1]);
        float e0 = __expf(acc[i0] - m2), e1 = __expf(acc[i1] - m2);
        float inv2 = 1.f / (e0 + e1);
        g_topi[2 * gwarp]     = i0; g_topw[2 * gwarp]     = e0 * inv2;
        g_topi[2 * gwarp + 1] = i1; g_topw[2 * gwarp + 1] = e1 * inv2;
        atomicAdd(&g_cnt[i0], 1);
        atomicAdd(&g_cnt[i1], 1);
    }
}

// Padded prefix-sum over 8 experts + loss / mean_probs written to output tail.
__global__ void k_offsets(float* __restrict__ out) {
    if (threadIdx.x != 0 || blockIdx.x != 0) return;
    int off = 0;
    for (int e = 0; e < NEXP; e++) {
        g_offpad[e] = off;
        off += ((g_cnt[e] + BM - 1) / BM) * BM;
    }
    g_offpad[NEXP] = off;
    float loss = 0.f;
    const float invT = 1.f / (float)T_TOK;
    for (int e = 0; e < NEXP; e++) {
        float m = g_probsum[e] * invT;
        out[(size_t)T_TOK * DIM + 1 + e] = m;      // mean_probs
        loss += m * m;
    }
    out[(size_t)T_TOK * DIM] = (float)NEXP * loss; // load_balance_loss
}

__global__ void k_scatter() {
    int t = blockIdx.x * blockDim.x + threadIdx.x;
    if (t >= 2 * T_TOK) return;
    int e = g_topi[t];
    int pos = g_offpad[e] + atomicAdd(&g_cursor[e], 1);
    g_perm[pos]  = t >> 1;
    g_permw[pos] = g_topw[t];
}

// ---------------------------------------------------------------------------
// GEMM1: [Mpad, 1024] x [1024, 8192] -> g_hg / g_hu. A rows gathered via perm.
// 128x128x16 tile, 256 threads, 8x8 per thread.
__global__ __launch_bounds__(256, 2) void k_gemm1(
    const float* __restrict__ x, const float* __restrict__ w_gate,
    const float* __restrict__ w_up) {
    __shared__ float As[BK][BM + 4];
    __shared__ float Bs[BK][BN];

    int mbase = blockIdx.y * BM;
    if (mbase >= g_offpad[NEXP]) return;
    int e = 0;
#pragma unroll
    for (int i = 0; i < NEXP; i++) if (mbase >= g_offpad[i + 1]) e = i + 1;

    int nt = blockIdx.x;                         // 0..63
    const int NTH = HID / BN;                    // 32
    const float* B = ((nt < NTH) ? w_gate : w_up)
                   + (size_t)e * DIM * HID + (size_t)(nt % NTH) * BN;
    float* Cout = (nt < NTH) ? g_hg : g_hu;
    int ncol = (nt % NTH) * BN;

    int tid  = threadIdx.x;
    int arow = tid >> 1;
    int akoff = (tid & 1) * 8;
    int tok = g_perm[mbase + arow];
    const float* aptr = (tok >= 0) ? (x + (size_t)tok * DIM + akoff) : nullptr;

    int brow = tid >> 4;                         // 0..15
    int bcol = (tid & 15) * 8;
    const float* bptr = B + (size_t)brow * HID + bcol;

    int tx = tid & 15, ty = tid >> 4;
    float acc[8][8];
#pragma unroll
    for (int i = 0; i < 8; i++)
#pragma unroll
        for (int j = 0; j < 8; j++) acc[i][j] = 0.f;

    for (int kk = 0; kk < DIM; kk += BK) {
        float4 a0, a1;
        if (aptr) {
            a0 = *(const float4*)(aptr + kk);
            a1 = *(const float4*)(aptr + kk + 4);
        } else {
            a0 = make_float4(0.f, 0.f, 0.f, 0.f); a1 = a0;
        }
        As[akoff + 0][arow] = a0.x; As[akoff + 1][arow] = a0.y;
        As[akoff + 2][arow] = a0.z; As[akoff + 3][arow] = a0.w;
        As[akoff + 4][arow] = a1.x; As[akoff + 5][arow] = a1.y;
        As[akoff + 6][arow] = a1.z; As[akoff + 7][arow] = a1.w;

        float4 b0 = *(const float4*)(bptr + (size_t)kk * HID);
        float4 b1 = *(const float4*)(bptr + (size_t)kk * HID + 4);
        *(float4*)&Bs[brow][bcol]     = b0;
        *(float4*)&Bs[brow][bcol + 4] = b1;
        __syncthreads();

#pragma unroll
        for (int k = 0; k < BK; k++) {
            float a[8], b[8];
            *(float4*)&a[0] = *(const float4*)&As[k][ty * 8];
            *(float4*)&a[4] = *(const float4*)&As[k][ty * 8 + 4];
            *(float4*)&b[0] = *(const float4*)&Bs[k][tx * 8];
            *(float4*)&b[4] = *(const float4*)&Bs[k][tx * 8 + 4];
#pragma unroll
            for (int i = 0; i < 8; i++)
#pragma unroll
                for (int j = 0; j < 8; j++) acc[i][j] += a[i] * b[j];
        }
        __syncthreads();
    }

#pragma unroll
    for (int i = 0; i < 8; i++) {
        size_t row = (size_t)(mbase + ty * 8 + i);
        float* cp = Cout + row * HID + ncol + tx * 8;
        *(float4*)cp       = *(float4*)&acc[i][0];
        *(float4*)(cp + 4) = *(float4*)&acc[i][4];
    }
}

// h = silu(pg) * pu, in place into g_hg. Done once (not per N-tile).
__global__ void k_silu() {
    size_t total = (size_t)g_offpad[NEXP] * HID;
    size_t stride = (size_t)gridDim.x * blockDim.x * 4;
    for (size_t idx = ((size_t)blockIdx.x * blockDim.x + threadIdx.x) * 4;
         idx < total; idx += stride) {
        float4 a = *(float4*)&g_hg[idx];
        float4 b = *(float4*)&g_hu[idx];
        float4 r;
        r.x = a.x * (1.f / (1.f + __expf(-a.x))) * b.x;
        r.y = a.y * (1.f / (1.f + __expf(-a.y))) * b.y;
        r.z = a.z * (1.f / (1.f + __expf(-a.z))) * b.z;
        r.w = a.w * (1.f / (1.f + __expf(-a.w))) * b.w;
        *(float4*)&g_hg[idx] = r;
    }
}

// GEMM2: [Mpad, 4096] x [4096, 1024] -> scaled atomic accumulate into out.
__global__ __launch_bounds__(256, 2) void k_gemm2(
    const float* __restrict__ w_down, float* __restrict__ out) {
    __shared__ float As[BK][BM + 4];
    __shared__ float Bs[BK][BN];

    int mbase = blockIdx.y * BM;
    if (mbase >= g_offpad[NEXP]) return;
    int e = 0;
#pragma unroll
    for (int i = 0; i < NEXP; i++) if (mbase >= g_offpad[i + 1]) e = i + 1;

    const float* B = w_down + (size_t)e * HID * DIM + (size_t)blockIdx.x * BN;

    int tid  = threadIdx.x;
    int arow = tid >> 1;
    int akoff = (tid & 1) * 8;
    const float* aptr = g_hg + (size_t)(mbase + arow) * HID + akoff;

    int brow = tid >> 4;
    int bcol = (tid & 15) * 8;
    const float* bptr = B + (size_t)brow * DIM + bcol;

    int tx = tid & 15, ty = tid >> 4;
    float acc[8][8];
#pragma unroll
    for (int i = 0; i < 8; i++)
#pragma unroll
        for (int j = 0; j < 8; j++) acc[i][j] = 0.f;

    for (int kk = 0; kk < HID; kk += BK) {
        float4 a0 = *(const float4*)(aptr + kk);
        float4 a1 = *(const float4*)(aptr + kk + 4);
        As[akoff + 0][arow] = a0.x; As[akoff + 1][arow] = a0.y;
        As[akoff + 2][arow] = a0.z; As[akoff + 3][arow] = a0.w;
        As[akoff + 4][arow] = a1.x; As[akoff + 5][arow] = a1.y;
        As[akoff + 6][arow] = a1.z; As[akoff + 7][arow] = a1.w;

        float4 b0 = *(const float4*)(bptr + (size_t)kk * DIM);
        float4 b1 = *(const float4*)(bptr + (size_t)kk * DIM + 4);
        *(float4*)&Bs[brow][bcol]     = b0;
        *(float4*)&Bs[brow][bcol + 4] = b1;
        __syncthreads();

#pragma unroll
        for (int k = 0; k < BK; k++) {
            float a[8], b[8];
            *(float4*)&a[0] = *(const float4*)&As[k][ty * 8];
            *(float4*)&a[4] = *(const float4*)&As[k][ty * 8 + 4];
            *(float4*)&b[0] = *(const float4*)&Bs[k][tx * 8];
            *(float4*)&b[4] = *(const float4*)&Bs[k][tx * 8 + 4];
#pragma unroll
            for (int i = 0; i < 8; i++)
#pragma unroll
                for (int j = 0; j < 8; j++) acc[i][j] += a[i] * b[j];
        }
        __syncthreads();
    }

#pragma unroll
    for (int i = 0; i < 8; i++) {
        int row = mbase + ty * 8 + i;
        int tok = g_perm[row];
        if (tok < 0) continue;
        float w = g_permw[row];
        float* op = out + (size_t)tok * DIM + (size_t)blockIdx.x * BN + tx * 8;
#pragma unroll
        for (int j = 0; j < 8; j++) atomicAdd(op + j, w * acc[i][j]);
    }
}

// ---------------------------------------------------------------------------
extern "C" void kernel_launch(void* const* d_in, const int* in_sizes, int n_in,
                              void* d_out, int out_size) {
    const float* x      = (const float*)d_in[0];
    const float* gate_w = (const float*)d_in[1];
    const float* w_gate = (const float*)d_in[2];
    const float* w_up   = (const float*)d_in[3];
    const float* w_down = (const float*)d_in[4];
    float* out = (float*)d_out;

    k_init<<<MAXPAD / 256, 256>>>();
    k_zero_out<<<2048, 256>>>((float4*)out, (T_TOK * DIM) / 4);
    k_gate<<<T_TOK / 8, 256>>>(x, gate_w);
    k_offsets<<<1, 32>>>(out);
    k_scatter<<<(2 * T_TOK) / 256, 256>>>();

    dim3 g1(2 * HID / BN, NMPAD);   // 64 x 136
    k_gemm1<<<g1, 256>>>(x, w_gate, w_up);

    k_silu<<<1184, 256>>>();

    dim3 g2(DIM / BN, NMPAD);       // 8 x 136
    k_gemm2<<<g2, 256>>>(w_down, out);
}

// round 4
// speedup vs baseline: 3.4675x; 3.4675x over previous
#include <cuda_runtime.h>
#include <cstdint>

#define T_TOK 8192
#define DIM   1024
#define HID   4096
#define NEXP  8
#define BM 128
#define BN 128
#define BK 32
#define NMPAD  136
#define MAXPAD (NMPAD * BM)

#define SA 36                       // A smem row stride (floats)
#define SB 136                      // B smem row stride (floats)
#define ASTG (BM * SA)              // 4608 floats
#define BSTG (BK * SB)              // 4352 floats
#define STGF (ASTG + BSTG)          // 8960 floats per stage
#define STGB (STGF * 4)             // 35840 bytes
#define SMEM_DYN (3 * STGB)         // 107520 bytes

// ---------------- scratch ----------------
__device__ float g_hg[(size_t)MAXPAD * HID];
__device__ float g_hu[(size_t)MAXPAD * HID];
__device__ float g_xc[(size_t)T_TOK * DIM];
__device__ float g_wgr[(size_t)NEXP * DIM * HID];
__device__ float g_wur[(size_t)NEXP * DIM * HID];
__device__ float g_wdr[(size_t)NEXP * HID * DIM];
__device__ int   g_perm[MAXPAD];
__device__ float g_permw[MAXPAD];
__device__ int   g_offpad[NEXP + 1];
__device__ int   g_cnt[NEXP];
__device__ int   g_cursor[NEXP];
__device__ float g_probsum[NEXP];
__device__ int   g_topi[T_TOK * 2];
__device__ float g_topw[T_TOK * 2];

// ---------------- helpers ----------------
__device__ __forceinline__ uint32_t smem_u32(const void* p) {
    uint32_t a;
    asm("{ .reg .u64 t; cvta.to.shared.u64 t, %1; cvt.u32.u64 %0, t; }"
        : "=r"(a) : "l"(p));
    return a;
}
__device__ __forceinline__ float frna(float x) {
    uint32_t o; asm("cvt.rna.tf32.f32 %0, %1;" : "=r"(o) : "f"(x));
    return __uint_as_float(o);
}
__device__ __forceinline__ void cp16(uint32_t d, const float* s, uint32_t sz) {
    asm volatile("cp.async.cg.shared.global [%0], [%1], 16, %2;"
                 :: "r"(d), "l"(s), "r"(sz));
}
#define CP_COMMIT() asm volatile("cp.async.commit_group;" ::: "memory")
#define CP_WAIT2()  asm volatile("cp.async.wait_group 2;" ::: "memory")

__device__ __forceinline__ void mma_tf32(float* c, const uint32_t* a,
                                         const uint32_t* b) {
    asm volatile(
        "mma.sync.aligned.m16n8k8.row.col.f32.tf32.tf32.f32 "
        "{%0,%1,%2,%3}, {%4,%5,%6,%7}, {%8,%9}, {%0,%1,%2,%3};"
        : "+f"(c[0]), "+f"(c[1]), "+f"(c[2]), "+f"(c[3])
        : "r"(a[0]), "r"(a[1]), "r"(a[2]), "r"(a[3]), "r"(b[0]), "r"(b[1]));
}

// ---------------- small kernels ----------------
__global__ void k_init() {
    int i = blockIdx.x * blockDim.x + threadIdx.x;
    if (i < NEXP) { g_cnt[i] = 0; g_cursor[i] = 0; g_probsum[i] = 0.f; }
    if (i < MAXPAD) g_perm[i] = -1;
}

__global__ void k_zero_out(float4* out, int n4) {
    float4 z = make_float4(0.f, 0.f, 0.f, 0.f);
    for (int i = blockIdx.x * blockDim.x + threadIdx.x; i < n4;
         i += gridDim.x * blockDim.x)
        out[i] = z;
}

// tf32-round copy. DST is a __device__ global selected INSIDE device code
// (passing __device__ symbols from host passes the host shadow address — R3 bug).
__global__ void k_round_sel(const float4* __restrict__ src, int n4, int sel) {
    float4* dst = (sel == 0) ? (float4*)g_xc
                : (sel == 1) ? (float4*)g_wgr
                : (sel == 2) ? (float4*)g_wur
                             : (float4*)g_wdr;
    for (int i = blockIdx.x * blockDim.x + threadIdx.x; i < n4;
         i += gridDim.x * blockDim.x) {
        float4 v = src[i];
        v.x = frna(v.x); v.y = frna(v.y); v.z = frna(v.z); v.w = frna(v.w);
        dst[i] = v;
    }
}

__global__ void k_gate(const float* __restrict__ x, const float* __restrict__ gw) {
    int gwarp = (blockIdx.x * blockDim.x + threadIdx.x) >> 5;
    int lane  = threadIdx.x & 31;
    if (gwarp >= T_TOK) return;
    const float* xr = x + (size_t)gwarp * DIM;

    float acc[NEXP];
#pragma unroll
    for (int e = 0; e < NEXP; e++) acc[e] = 0.f;
    for (int i = lane; i < DIM; i += 32) {
        float xv = xr[i];
        float4 g0 = *(const float4*)(gw + (size_t)i * NEXP);
        float4 g1 = *(const float4*)(gw + (size_t)i * NEXP + 4);
        acc[0] += xv * g0.x; acc[1] += xv * g0.y;
        acc[2] += xv * g0.z; acc[3] += xv * g0.w;
        acc[4] += xv * g1.x; acc[5] += xv * g1.y;
        acc[6] += xv * g1.z; acc[7] += xv * g1.w;
    }
#pragma unroll
    for (int off = 16; off > 0; off >>= 1)
#pragma unroll
        for (int e = 0; e < NEXP; e++)
            acc[e] += __shfl_xor_sync(0xffffffffu, acc[e], off);

    float mx = acc[0];
#pragma unroll
    for (int e = 1; e < NEXP; e++) mx = fmaxf(mx, acc[e]);
    float p[NEXP], s = 0.f;
#pragma unroll
    for (int e = 0; e < NEXP; e++) { p[e] = __expf(acc[e] - mx); s += p[e]; }
    float inv = 1.f / s;
    if (lane < NEXP) atomicAdd(&g_probsum[lane], p[lane] * inv);

    if (lane == 0) {
        int i0 = 0;
#pragma unroll
        for (int e = 1; e < NEXP; e++) if (acc[e] > acc[i0]) i0 = e;
        int i1 = (i0 == 0) ? 1 : 0;
#pragma unroll
        for (int e = 0; e < NEXP; e++)
            if (e != i0 && acc[e] > acc[i1]) i1 = e;
        float m2 = fmaxf(acc[i0], acc[i1]);
        float e0 = __expf(acc[i0] - m2), e1 = __expf(acc[i1] - m2);
        float inv2 = 1.f / (e0 + e1);
        g_topi[2 * gwarp]     = i0; g_topw[2 * gwarp]     = e0 * inv2;
        g_topi[2 * gwarp + 1] = i1; g_topw[2 * gwarp + 1] = e1 * inv2;
        atomicAdd(&g_cnt[i0], 1);
        atomicAdd(&g_cnt[i1], 1);
    }
}

__global__ void k_offsets(float* __restrict__ out) {
    if (threadIdx.x != 0 || blockIdx.x != 0) return;
    int off = 0;
    for (int e = 0; e < NEXP; e++) {
        g_offpad[e] = off;
        off += ((g_cnt[e] + BM - 1) / BM) * BM;
    }
    g_offpad[NEXP] = off;
    float loss = 0.f;
    const float invT = 1.f / (float)T_TOK;
    for (int e = 0; e < NEXP; e++) {
        float m = g_probsum[e] * invT;
        out[(size_t)T_TOK * DIM + 1 + e] = m;
        loss += m * m;
    }
    out[(size_t)T_TOK * DIM] = (float)NEXP * loss;
}

__global__ void k_scatter() {
    int t = blockIdx.x * blockDim.x + threadIdx.x;
    if (t >= 2 * T_TOK) return;
    int e = g_topi[t];
    int pos = g_offpad[e] + atomicAdd(&g_cursor[e], 1);
    g_perm[pos]  = t >> 1;
    g_permw[pos] = g_topw[t];
}

__global__ void k_silu() {
    size_t total = (size_t)g_offpad[NEXP] * HID;
    size_t stride = (size_t)gridDim.x * blockDim.x * 4;
    for (size_t idx = ((size_t)blockIdx.x * blockDim.x + threadIdx.x) * 4;
         idx < total; idx += stride) {
        float4 a = *(float4*)&g_hg[idx];
        float4 b = *(float4*)&g_hu[idx];
        float4 r;
        r.x = frna(a.x * (1.f / (1.f + __expf(-a.x))) * b.x);
        r.y = frna(a.y * (1.f / (1.f + __expf(-a.y))) * b.y);
        r.z = frna(a.z * (1.f / (1.f + __expf(-a.z))) * b.z);
        r.w = frna(a.w * (1.f / (1.f + __expf(-a.w))) * b.w);
        *(float4*)&g_hg[idx] = r;
    }
}

// ---------------- GEMM1: [Mpad,1024] x [1024,4096] for gate & up ----------------
__global__ __launch_bounds__(256) void k_gemm1_mma() {
    extern __shared__ float sm[];
    int total = g_offpad[NEXP];
    int mbase = blockIdx.y * BM;
    if (mbase >= total) return;
    int e = 0;
#pragma unroll
    for (int i = 0; i < NEXP; i++) if (mbase >= g_offpad[i + 1]) e = i + 1;

    int bx = blockIdx.x;                 // 0..63 : [gate 0-31 | up 32-63]
    const float* W = ((bx < 32) ? g_wgr : g_wur) + (size_t)e * DIM * HID;
    float* C = (bx < 32) ? g_hg : g_hu;
    int ncol = (bx & 31) * BN;

    int tid = threadIdx.x;
    uint32_t smb = smem_u32(sm);

    int arow0 = tid >> 3, akf = (tid & 7) * 4;
    uint32_t adst[4]; const float* asrc[4]; uint32_t asz[4];
#pragma unroll
    for (int p = 0; p < 4; p++) {
        int row = arow0 + p * 32;
        adst[p] = (uint32_t)(row * SA + akf) * 4;
        int tok = g_perm[mbase + row];
        asrc[p] = g_xc + ((tok >= 0) ? (size_t)tok * DIM : 0) + akf;
        asz[p]  = (tok >= 0) ? 16u : 0u;
    }
    int bkr0 = tid >> 5, bnf = (tid & 31) * 4;
    uint32_t bdst[4]; const float* bsrc[4];
#pragma unroll
    for (int p = 0; p < 4; p++) {
        int kr = bkr0 + p * 8;
        bdst[p] = (uint32_t)(ASTG + kr * SB + bnf) * 4;
        bsrc[p] = W + (size_t)kr * HID + ncol + bnf;
    }

    int lane = tid & 31, gid = lane >> 2, tig = lane & 3;
    int wm = (tid >> 5) & 3, wn = tid >> 7;
    int r0 = wm * 32 + gid, cb = wn * 64 + gid;

    float acc[2][8][4];
#pragma unroll
    for (int mt = 0; mt < 2; mt++)
#pragma unroll
        for (int nt = 0; nt < 8; nt++)
#pragma unroll
            for (int q = 0; q < 4; q++) acc[mt][nt][q] = 0.f;

    const int NT = DIM / BK;             // 32
#pragma unroll
    for (int t = 0; t < 3; t++) {
        uint32_t base = smb + t * STGB;
        int k0 = t * BK;
#pragma unroll
        for (int p = 0; p < 4; p++) cp16(base + adst[p], asrc[p] + k0, asz[p]);
#pragma unroll
        for (int p = 0; p < 4; p++)
            cp16(base + bdst[p], bsrc[p] + (size_t)k0 * HID, 16);
        CP_COMMIT();
    }

    for (int i = 0; i < NT; i++) {
        CP_WAIT2();
        __syncthreads();
        const uint32_t* Au = (const uint32_t*)(sm + (i % 3) * STGF);
        const uint32_t* Bu = Au + ASTG;
#pragma unroll
        for (int ks = 0; ks < 4; ks++) {
            int k = ks * 8;
            uint32_t a[2][4], b[8][2];
#pragma unroll
            for (int mt = 0; mt < 2; mt++) {
                int rr = r0 + mt * 16;
                a[mt][0] = Au[rr * SA + k + tig];
                a[mt][1] = Au[(rr + 8) * SA + k + tig];
                a[mt][2] = Au[rr * SA + k + 4 + tig];
                a[mt][3] = Au[(rr + 8) * SA + k + 4 + tig];
            }
#pragma unroll
            for (int nt = 0; nt < 8; nt++) {
                int cc = cb + nt * 8;
                b[nt][0] = Bu[(k + tig) * SB + cc];
                b[nt][1] = Bu[(k + tig + 4) * SB + cc];
            }
#pragma unroll
            for (int mt = 0; mt < 2; mt++)
#pragma unroll
                for (int nt = 0; nt < 8; nt++)
                    mma_tf32(acc[mt][nt], a[mt], b[nt]);
        }
        __syncthreads();
        int t = i + 3;
        if (t < NT) {
            uint32_t base = smb + (t % 3) * STGB;
            int k0 = t * BK;
#pragma unroll
            for (int p = 0; p < 4; p++) cp16(base + adst[p], asrc[p] + k0, asz[p]);
#pragma unroll
            for (int p = 0; p < 4; p++)
                cp16(base + bdst[p], bsrc[p] + (size_t)k0 * HID, 16);
        }
        CP_COMMIT();
    }

#pragma unroll
    for (int mt = 0; mt < 2; mt++) {
        int r = mbase + wm * 32 + mt * 16 + gid;
#pragma unroll
        for (int nt = 0; nt < 8; nt++) {
            int c = ncol + wn * 64 + nt * 8 + 2 * tig;
            *(float2*)&C[(size_t)r * HID + c] =
                make_float2(acc[mt][nt][0], acc[mt][nt][1]);
            *(float2*)&C[(size_t)(r + 8) * HID + c] =
                make_float2(acc[mt][nt][2], acc[mt][nt][3]);
        }
    }
}

// ---------------- GEMM2: [Mpad,4096] x [4096,1024], atomic epilogue -------------
__global__ __launch_bounds__(256) void k_gemm2_mma(float* __restrict__ out) {
    extern __shared__ float sm[];
    int total = g_offpad[NEXP];
    int mbase = blockIdx.y * BM;
    if (mbase >= total) return;
    int e = 0;
#pragma unroll
    for (int i = 0; i < NEXP; i++) if (mbase >= g_offpad[i + 1]) e = i + 1;

    const float* W = g_wdr + (size_t)e * HID * DIM;
    int ncol = blockIdx.x * BN;

    int tid = threadIdx.x;
    uint32_t smb = smem_u32(sm);

    int arow0 = tid >> 3, akf = (tid & 7) * 4;
    uint32_t adst[4]; const float* asrc[4];
#pragma unroll
    for (int p = 0; p < 4; p++) {
        int row = arow0 + p * 32;
        adst[p] = (uint32_t)(row * SA + akf) * 4;
        asrc[p] = g_hg + (size_t)(mbase + row) * HID + akf;
    }
    int bkr0 = tid >> 5, bnf = (tid & 31) * 4;
    uint32_t bdst[4]; const float* bsrc[4];
#pragma unroll
    for (int p = 0; p < 4; p++) {
        int kr = bkr0 + p * 8;
        bdst[p] = (uint32_t)(ASTG + kr * SB + bnf) * 4;
        bsrc[p] = W + (size_t)kr * DIM + ncol + bnf;
    }

    int lane = tid & 31, gid = lane >> 2, tig = lane & 3;
    int wm = (tid >> 5) & 3, wn = tid >> 7;
    int r0 = wm * 32 + gid, cb = wn * 64 + gid;

    float acc[2][8][4];
#pragma unroll
    for (int mt = 0; mt < 2; mt++)
#pragma unroll
        for (int nt = 0; nt < 8; nt++)
#pragma unroll
            for (int q = 0; q < 4; q++) acc[mt][nt][q] = 0.f;

    const int NT = HID / BK;            // 128
#pragma unroll
    for (int t = 0; t < 3; t++) {
        uint32_t base = smb + t * STGB;
        int k0 = t * BK;
#pragma unroll
        for (int p = 0; p < 4; p++) cp16(base + adst[p], asrc[p] + k0, 16);
#pragma unroll
        for (int p = 0; p < 4; p++)
            cp16(base + bdst[p], bsrc[p] + (size_t)k0 * DIM, 16);
        CP_COMMIT();
    }

    for (int i = 0; i < NT; i++) {
        CP_WAIT2();
        __syncthreads();
        const uint32_t* Au = (const uint32_t*)(sm + (i % 3) * STGF);
        const uint32_t* Bu = Au + ASTG;
#pragma unroll
        for (int ks = 0; ks < 4; ks++) {
            int k = ks * 8;
            uint32_t a[2][4], b[8][2];
#pragma unroll
            for (int mt = 0; mt < 2; mt++) {
                int rr = r0 + mt * 16;
                a[mt][0] = Au[rr * SA + k + tig];
                a[mt][1] = Au[(rr + 8) * SA + k + tig];
                a[mt][2] = Au[rr * SA + k + 4 + tig];
                a[mt][3] = Au[(rr + 8) * SA + k + 4 + tig];
            }
#pragma unroll
            for (int nt = 0; nt < 8; nt++) {
                int cc = cb + nt * 8;
                b[nt][0] = Bu[(k + tig) * SB + cc];
                b[nt][1] = Bu[(k + tig + 4) * SB + cc];
            }
#pragma unroll
            for (int mt = 0; mt < 2; mt++)
#pragma unroll
                for (int nt = 0; nt < 8; nt++)
                    mma_tf32(acc[mt][nt], a[mt], b[nt]);
        }
        __syncthreads();
        int t = i + 3;
        if (t < NT) {
            uint32_t base = smb + (t % 3) * STGB;
            int k0 = t * BK;
#pragma unroll
            for (int p = 0; p < 4; p++) cp16(base + adst[p], asrc[p] + k0, 16);
#pragma unroll
            for (int p = 0; p < 4; p++)
                cp16(base + bdst[p], bsrc[p] + (size_t)k0 * DIM, 16);
        }
        CP_COMMIT();
    }

#pragma unroll
    for (int mt = 0; mt < 2; mt++) {
        int slot = mbase + wm * 32 + mt * 16 + gid;
        int tok0 = g_perm[slot],     tok1 = g_perm[slot + 8];
        float w0 = g_permw[slot],    w1 = g_permw[slot + 8];
#pragma unroll
        for (int nt = 0; nt < 8; nt++) {
            int c = ncol + wn * 64 + nt * 8 + 2 * tig;
            if (tok0 >= 0) {
                float* op = out + (size_t)tok0 * DIM + c;
                atomicAdd(op,     w0 * acc[mt][nt][0]);
                atomicAdd(op + 1, w0 * acc[mt][nt][1]);
            }
            if (tok1 >= 0) {
                float* op = out + (size_t)tok1 * DIM + c;
                atomicAdd(op,     w1 * acc[mt][nt][2]);
                atomicAdd(op + 1, w1 * acc[mt][nt][3]);
            }
        }
    }
}

// ---------------- launch ----------------
extern "C" void kernel_launch(void* const* d_in, const int* in_sizes, int n_in,
                              void* d_out, int out_size) {
    const float* x      = (const float*)d_in[0];
    const float* gate_w = (const float*)d_in[1];
    const float* w_gate = (const float*)d_in[2];
    const float* w_up   = (const float*)d_in[3];
    const float* w_down = (const float*)d_in[4];
    float* out = (float*)d_out;

    cudaFuncSetAttribute(k_gemm1_mma, cudaFuncAttributeMaxDynamicSharedMemorySize,
                         SMEM_DYN);
    cudaFuncSetAttribute(k_gemm2_mma, cudaFuncAttributeMaxDynamicSharedMemorySize,
                         SMEM_DYN);

    k_init<<<MAXPAD / 256, 256>>>();
    k_zero_out<<<2048, 256>>>((float4*)out, (T_TOK * DIM) / 4);
    k_gate<<<T_TOK / 8, 256>>>(x, gate_w);
    k_offsets<<<1, 32>>>(out);
    k_scatter<<<(2 * T_TOK) / 256, 256>>>();

    const int xn4 = T_TOK * DIM / 4;
    const int wn4 = NEXP * DIM * HID / 4;
    k_round_sel<<<2048, 256>>>((const float4*)x,      xn4, 0);
    k_round_sel<<<8192, 256>>>((const float4*)w_gate, wn4, 1);
    k_round_sel<<<8192, 256>>>((const float4*)w_up,   wn4, 2);
    k_round_sel<<<8192, 256>>>((const float4*)w_down, wn4, 3);

    k_gemm1_mma<<<dim3(2 * HID / BN, NMPAD), 256, SMEM_DYN>>>();
    k_silu<<<1184, 256>>>();
    k_gemm2_mma<<<dim3(DIM / BN, NMPAD), 256, SMEM_DYN>>>(out);
}